// round 1
// baseline (speedup 1.0000x reference)
#include <cuda_runtime.h>
#include <stdint.h>

#define N_ENTS 50000
#define N_RELS 500
#define N_TOT  50500
#define EMB    256
#define N_EDGES 400000
#define BATCH  512
#define BN_EPS 1e-5f

// ---------------- scratch (__device__ globals, no allocations) ----------------
__device__ float g_XR[(size_t)N_TOT * EMB];      // [X ; R] contiguous
__device__ float g_sup[(size_t)N_TOT * EMB];     // support buffer
__device__ float g_agg[(size_t)N_TOT * EMB];     // segment-sum accumulator
__device__ float g_XRrf[(size_t)N_TOT * EMB];    // tanh(bn(agg)) for XR graph
__device__ float g_Xef[(size_t)N_ENTS * EMB];    // tanh(bn(agg)) for X graph
__device__ float g_hr[(size_t)BATCH * EMB];      // score intermediate
__device__ float g_HamT[EMB * EMB];              // transposed hamilton (gcn)
__device__ float g_H1T[EMB * EMB];               // lin hamilton part 1 (perm folded)
__device__ float g_H2T[EMB * EMB];               // lin hamilton part 2 (perm folded)
__device__ float g_csum[EMB];
__device__ float g_csq[EMB];
__device__ float g_scale[EMB];
__device__ float g_shift[EMB];

// quaternion block tables: ham[k=a*rw+u, c=b*64+v] = sign[a][b] * W[u, comp[a][b]*64+v]
__constant__ int   c_comp[4][4] = {{0,1,2,3},{1,0,3,2},{2,3,0,1},{3,2,1,0}};
__constant__ float c_sign[4][4] = {{ 1.f, 1.f, 1.f, 1.f},
                                   {-1.f, 1.f, 1.f,-1.f},
                                   {-1.f,-1.f, 1.f, 1.f},
                                   {-1.f, 1.f,-1.f, 1.f}};

// ---------------- hamilton builders (store TRANSPOSED: HT[c*K + k]) ----------------
__global__ void build_hamT(const float* __restrict__ W, float* __restrict__ HT) {
    // gcn: W is 64x256, ham is 256x256
    int idx = blockIdx.x * blockDim.x + threadIdx.x;       // c*256 + k
    if (idx >= EMB * EMB) return;
    int c = idx >> 8, k = idx & 255;
    int a = k >> 6, u = k & 63, b = c >> 6, v = c & 63;
    HT[idx] = c_sign[a][b] * W[u * EMB + c_comp[a][b] * 64 + v];
}

__global__ void build_hamLPT(const float* __restrict__ W, float* __restrict__ H1,
                             float* __restrict__ H2) {
    // lin: W is 128x256, ham is 512x256; fold Xcat interleave permutation:
    // Xef col j -> ham row p=128*(j/64)+(j%64);  Xrf col j -> p+64
    int c = blockIdx.x, j = threadIdx.x;
    int q = j >> 6, s = j & 63;
    int b = c >> 6, v = c & 63;
    int pe = 128 * q + s;
    int pr = pe + 64;
    int a1 = pe >> 7, u1 = pe & 127;
    int a2 = pr >> 7, u2 = pr & 127;
    H1[c * EMB + j] = c_sign[a1][b] * W[u1 * EMB + c_comp[a1][b] * 64 + v];
    H2[c * EMB + j] = c_sign[a2][b] * W[u2 * EMB + c_comp[a2][b] * 64 + v];
}

// ---------------- generic NT GEMM: C[M,N] (op)= A[M,K] * B[N,K]^T ----------------
enum { EPI_STORE = 0, EPI_ACC = 1, EPI_SIG = 2 };

template <int EPI>
__global__ void __launch_bounds__(256)
gemm_nt(const float* __restrict__ A, const float* __restrict__ Bm,
        float* __restrict__ C, int M, int N, int K) {
    __shared__ float As[16][68];
    __shared__ float Bs[16][68];
    const int tid = threadIdx.x;
    const int tx = tid & 15, ty = tid >> 4;
    const int m0 = blockIdx.y * 64, n0 = blockIdx.x * 64;
    const int lr = tid >> 2;            // 0..63 tile row
    const int lc = (tid & 3) << 2;      // 0,4,8,12 k offset

    float acc[4][4];
#pragma unroll
    for (int i = 0; i < 4; i++)
#pragma unroll
        for (int j = 0; j < 4; j++) acc[i][j] = 0.f;

    const int am = m0 + lr;
    const int bn = n0 + lr;
    const bool aval = am < M, bval = bn < N;
    const float* Ap = A + (size_t)am * K + lc;
    const float* Bp = Bm + (size_t)bn * K + lc;

    for (int kk = 0; kk < K; kk += 16) {
        float4 av = make_float4(0.f, 0.f, 0.f, 0.f);
        float4 bv = make_float4(0.f, 0.f, 0.f, 0.f);
        if (aval) av = *(const float4*)(Ap + kk);
        if (bval) bv = *(const float4*)(Bp + kk);
        As[lc + 0][lr] = av.x; As[lc + 1][lr] = av.y;
        As[lc + 2][lr] = av.z; As[lc + 3][lr] = av.w;
        Bs[lc + 0][lr] = bv.x; Bs[lc + 1][lr] = bv.y;
        Bs[lc + 2][lr] = bv.z; Bs[lc + 3][lr] = bv.w;
        __syncthreads();
#pragma unroll
        for (int k = 0; k < 16; k++) {
            float a[4], b[4];
#pragma unroll
            for (int i = 0; i < 4; i++) a[i] = As[k][ty * 4 + i];
#pragma unroll
            for (int j = 0; j < 4; j++) b[j] = Bs[k][tx * 4 + j];
#pragma unroll
            for (int i = 0; i < 4; i++)
#pragma unroll
                for (int j = 0; j < 4; j++) acc[i][j] = fmaf(a[i], b[j], acc[i][j]);
        }
        __syncthreads();
    }

#pragma unroll
    for (int i = 0; i < 4; i++) {
        int r = m0 + ty * 4 + i;
        if (r >= M) continue;
#pragma unroll
        for (int j = 0; j < 4; j++) {
            int col = n0 + tx * 4 + j;
            if (col >= N) continue;
            size_t idx = (size_t)r * N + col;
            float v = acc[i][j];
            if (EPI == EPI_ACC) v += C[idx];
            if (EPI == EPI_SIG) v = 1.f / (1.f + __expf(-v));
            C[idx] = v;
        }
    }
}

// ---------------- SpMM: agg[row] += val * sup[col]  (64 lanes/edge, float4 red) --------
__global__ void spmm(const int* __restrict__ rows, const int* __restrict__ cols,
                     const float* __restrict__ vals, const float* __restrict__ sup,
                     float* __restrict__ agg, int ne) {
    int e = blockIdx.x * 4 + (threadIdx.x >> 6);
    if (e >= ne) return;
    int t = threadIdx.x & 63;
    int r = rows[e], c = cols[e];
    float v = vals[e];
    float4 s = *(const float4*)(sup + (size_t)c * EMB + t * 4);
    float4 a = make_float4(v * s.x, v * s.y, v * s.z, v * s.w);
    atomicAdd((float4*)(agg + (size_t)r * EMB + t * 4), a);
}

// ---------------- node batchnorm (axis 0 over n rows) ----------------
__global__ void colstats(const float* __restrict__ X, int n) {
    int c = threadIdx.x;
    int r0 = blockIdx.x * 256;
    int r1 = min(r0 + 256, n);
    float s = 0.f, s2 = 0.f;
    for (int r = r0; r < r1; r++) {
        float v = X[(size_t)r * EMB + c];
        s += v; s2 += v * v;
    }
    atomicAdd(&g_csum[c], s);
    atomicAdd(&g_csq[c], s2);
}

__global__ void bn_final(const float* __restrict__ gamma, const float* __restrict__ beta,
                         float inv_n) {
    int c = threadIdx.x;
    float m = g_csum[c] * inv_n;
    float var = g_csq[c] * inv_n - m * m;
    float sc = rsqrtf(var + BN_EPS) * gamma[c];
    g_scale[c] = sc;
    g_shift[c] = beta[c] - m * sc;
}

__global__ void bn_tanh(const float* __restrict__ X, float* __restrict__ Y, int n4) {
    int i = blockIdx.x * blockDim.x + threadIdx.x;
    if (i >= n4) return;
    int c0 = (i * 4) & 255;
    float4 x = ((const float4*)X)[i];
    float4 y;
    float* xs = &x.x;
    float* ys = &y.x;
#pragma unroll
    for (int j = 0; j < 4; j++) {
        float z = xs[j] * g_scale[c0 + j] + g_shift[c0 + j];
        float e = __expf(-2.f * fabsf(z));
        float t = (1.f - e) / (1.f + e);
        ys[j] = copysignf(t, z);
    }
    ((float4*)Y)[i] = y;
}

// ---------------- score head ----------------
__global__ void vecvec(const float* __restrict__ X, const float* __restrict__ R,
                       const int* __restrict__ e1, const int* __restrict__ ri,
                       float* __restrict__ hr) {
    int b = blockIdx.x;        // 0..511
    int s = threadIdx.x;       // 0..63
    const float* h = X + (size_t)e1[b] * EMB;
    const float* p = R + (size_t)ri[b] * EMB;
    float pr = p[s], pi = p[64 + s], pj = p[128 + s], pk = p[192 + s];
    float inv = rsqrtf(pr * pr + pi * pi + pj * pj + pk * pk);
    pr *= inv; pi *= inv; pj *= inv; pk *= inv;
    float qr = h[s], qi = h[64 + s], qj = h[128 + s], qk = h[192 + s];
    float* o = hr + (size_t)b * EMB;
    o[s]       = qr * pr - qi * pi - qj * pj - qk * pk;
    o[64 + s]  = qi * pr + qr * pi - qk * pj + qj * pk;
    o[128 + s] = qj * pr + qk * pi + qr * pj - qi * pk;
    o[192 + s] = qk * pr - qj * pi + qi * pj + qr * pk;
}

__global__ void bn_batch(float* __restrict__ hr, const float* __restrict__ gamma,
                         const float* __restrict__ beta) {
    int c = threadIdx.x;
    float s = 0.f, s2 = 0.f;
    for (int b = 0; b < BATCH; b++) {
        float v = hr[(size_t)b * EMB + c];
        s += v; s2 += v * v;
    }
    float m = s * (1.f / BATCH);
    float var = s2 * (1.f / BATCH) - m * m;
    float sc = rsqrtf(var + BN_EPS) * gamma[c];
    float sh = beta[c] - m * sc;
    for (int b = 0; b < BATCH; b++)
        hr[(size_t)b * EMB + c] = hr[(size_t)b * EMB + c] * sc + sh;
}

// ---------------- host orchestration ----------------
static void run_score(int s, const int* e1, const int* ri,
                      const float* bsg, const float* bsb,
                      float* XR, float* hr, float* out) {
    vecvec<<<BATCH, 64>>>(XR, XR + (size_t)N_ENTS * EMB, e1, ri, hr);
    bn_batch<<<1, EMB>>>(hr, bsg + s * EMB, bsb + s * EMB);
    dim3 g((N_ENTS + 63) / 64, (BATCH + 63) / 64);
    gemm_nt<EPI_SIG><<<g, 256>>>(hr, XR, out + (size_t)s * BATCH * N_ENTS,
                                 BATCH, N_ENTS, EMB);
}

extern "C" void kernel_launch(void* const* d_in, const int* in_sizes, int n_in,
                              void* d_out, int out_size) {
    const int*   e1      = (const int*)d_in[0];
    const int*   ri      = (const int*)d_in[1];
    const float* emb     = (const float*)d_in[2];
    const float* gcn1_w  = (const float*)d_in[3];
    const float* gcn2_w  = (const float*)d_in[4];
    const float* g1_gam  = (const float*)d_in[5];
    const float* g1_bet  = (const float*)d_in[6];
    const float* g2_gam  = (const float*)d_in[7];
    const float* g2_bet  = (const float*)d_in[8];
    const float* lin     = (const float*)d_in[9];
    const float* bsg     = (const float*)d_in[10];
    const float* bsb     = (const float*)d_in[11];
    const int*   a_rows  = (const int*)d_in[12];
    const int*   a_cols  = (const int*)d_in[13];
    const float* a_vals  = (const float*)d_in[14];
    const int*   ar_rows = (const int*)d_in[15];
    const int*   ar_cols = (const int*)d_in[16];
    const float* ar_vals = (const float*)d_in[17];
    float* out = (float*)d_out;

    float *XR, *sup, *agg, *XRrf, *Xef, *hr, *HamT, *H1T, *H2T, *csum, *csq;
    cudaGetSymbolAddress((void**)&XR,   g_XR);
    cudaGetSymbolAddress((void**)&sup,  g_sup);
    cudaGetSymbolAddress((void**)&agg,  g_agg);
    cudaGetSymbolAddress((void**)&XRrf, g_XRrf);
    cudaGetSymbolAddress((void**)&Xef,  g_Xef);
    cudaGetSymbolAddress((void**)&hr,   g_hr);
    cudaGetSymbolAddress((void**)&HamT, g_HamT);
    cudaGetSymbolAddress((void**)&H1T,  g_H1T);
    cudaGetSymbolAddress((void**)&H2T,  g_H2T);
    cudaGetSymbolAddress((void**)&csum, g_csum);
    cudaGetSymbolAddress((void**)&csq,  g_csq);

    // X,R <- embeddings (contiguous: XR buffer == [X ; R])
    cudaMemcpyAsync(XR, emb, (size_t)N_TOT * EMB * sizeof(float),
                    cudaMemcpyDeviceToDevice);

    run_score(0, e1, ri, bsg, bsb, XR, hr, out);

    for (int l = 0; l < 2; l++) {
        // ---- XR branch: XRrf = tanh(bn(segsum(adjr, XR @ Ham(gcn2)))) ----
        build_hamT<<<(EMB * EMB + 255) / 256, 256>>>(gcn2_w + (size_t)l * 64 * EMB, HamT);
        gemm_nt<EPI_STORE><<<dim3(4, (N_TOT + 63) / 64), 256>>>(XR, HamT, sup,
                                                                N_TOT, EMB, EMB);
        cudaMemsetAsync(agg, 0, (size_t)N_TOT * EMB * sizeof(float));
        spmm<<<(N_EDGES + 3) / 4, 256>>>(ar_rows, ar_cols, ar_vals, sup, agg, N_EDGES);
        cudaMemsetAsync(csum, 0, EMB * sizeof(float));
        cudaMemsetAsync(csq,  0, EMB * sizeof(float));
        colstats<<<(N_TOT + 255) / 256, EMB>>>(agg, N_TOT);
        bn_final<<<1, EMB>>>(g2_gam + l * EMB, g2_bet + l * EMB, 1.f / N_TOT);
        bn_tanh<<<((size_t)N_TOT * 64 + 255) / 256, 256>>>(agg, XRrf, N_TOT * 64);

        // ---- X branch: Xef = tanh(bn(segsum(adj, X @ Ham(gcn1)))) ----
        build_hamT<<<(EMB * EMB + 255) / 256, 256>>>(gcn1_w + (size_t)l * 64 * EMB, HamT);
        gemm_nt<EPI_STORE><<<dim3(4, (N_ENTS + 63) / 64), 256>>>(XR, HamT, sup,
                                                                 N_ENTS, EMB, EMB);
        cudaMemsetAsync(agg, 0, (size_t)N_ENTS * EMB * sizeof(float));
        spmm<<<(N_EDGES + 3) / 4, 256>>>(a_rows, a_cols, a_vals, sup, agg, N_EDGES);
        cudaMemsetAsync(csum, 0, EMB * sizeof(float));
        cudaMemsetAsync(csq,  0, EMB * sizeof(float));
        colstats<<<(N_ENTS + 255) / 256, EMB>>>(agg, N_ENTS);
        bn_final<<<1, EMB>>>(g1_gam + l * EMB, g1_bet + l * EMB, 1.f / N_ENTS);
        bn_tanh<<<((size_t)N_ENTS * 64 + 255) / 256, 256>>>(agg, Xef, N_ENTS * 64);

        // ---- lin: X_new = Xef @ H1^T + Xrf @ H2^T (Xcat permutation folded in) ----
        build_hamLPT<<<EMB, EMB>>>(lin + (size_t)l * 128 * EMB, H1T, H2T);
        gemm_nt<EPI_STORE><<<dim3(4, (N_ENTS + 63) / 64), 256>>>(Xef, H1T, XR,
                                                                 N_ENTS, EMB, EMB);
        gemm_nt<EPI_ACC><<<dim3(4, (N_ENTS + 63) / 64), 256>>>(XRrf, H2T, XR,
                                                               N_ENTS, EMB, EMB);
        // R <- XRrf[N_ENTS:]
        cudaMemcpyAsync(XR + (size_t)N_ENTS * EMB, XRrf + (size_t)N_ENTS * EMB,
                        (size_t)N_RELS * EMB * sizeof(float),
                        cudaMemcpyDeviceToDevice);

        run_score(l + 1, e1, ri, bsg, bsb, XR, hr, out);
    }
}